// round 1
// baseline (speedup 1.0000x reference)
#include <cuda_runtime.h>
#include <math.h>

#define SLEN 256
#define BSZ  64
#define DIM  1024
#define HID  512
#define NT   17
#define G4   (4*HID)    // 2048 gate rows per direction
#define NCOLS (2*G4)    // 4096 combined columns (fwd+bwd)
#define NROWS (SLEN*BSZ)

// ---------------- device scratch (no allocations allowed) ----------------
__device__ float d_xg[(size_t)2*SLEN*G4*BSZ];          // [dir][s][g][b]  256MB
__device__ float d_hbuf[2][2*HID*BSZ];                 // ping-pong [p][dir][j][b]
__device__ float d_cbuf[2][2*HID*BSZ];
__device__ float d_hall[(size_t)SLEN*2*HID*BSZ];       // [s][f=dir*512+j][b] 64MB
__device__ float d_bias[NCOLS];
__device__ float d_mean[2*HID], d_rstd[2*HID];
__device__ float d_A[NT*2*HID];
__device__ float d_Cc[NT];
__device__ float d_E[(size_t)BSZ*SLEN*NT];             // [b][s][t]
__device__ int   d_bp[(size_t)BSZ*SLEN*NT];
__device__ int   d_maskI[SLEN*BSZ];                    // [s][b]
__device__ float d_lossParts[BSZ];

__device__ __forceinline__ float sigm(float x){ return 1.f/(1.f+expf(-x)); }

// ---------------- prep: bias fold, mask normalize, h0/c0 zero ----------------
__global__ void prep_kernel(const float* __restrict__ bif, const float* __restrict__ bhf,
                            const float* __restrict__ bib, const float* __restrict__ bhb,
                            const void* __restrict__ maskraw)
{
    int idx = blockIdx.x*blockDim.x + threadIdx.x;     // grid covers 65536
    if (idx < NCOLS){
        int dir = idx >> 11, g = idx & 2047;
        d_bias[idx] = dir ? (bib[g]+bhb[g]) : (bif[g]+bhf[g]);
    }
    if (idx < SLEN*BSZ){
        const unsigned char* rb = (const unsigned char*)maskraw;
        // mask[0][1] is always true (lengths >= SL/2). bool layout -> byte1==1,
        // int32/float32 layout -> byte1==0.
        bool isbool = (rb[1] != 0);
        int v;
        if (isbool) v = (rb[idx] != 0);
        else        v = (((const int*)maskraw)[idx] != 0);  // also handles f32 bit pattern
        d_maskI[idx] = v;
    }
    if (idx < 2*HID*BSZ){
        d_hbuf[0][idx] = 0.f;
        d_cbuf[0][idx] = 0.f;
    }
}

// ---------------- big input GEMM: xg[dir][s][g][b] = X@W^T + bias ----------------
// M=16384 (s*64+b), K=1024, N=4096 (dir*2048+g). 128x128 tile, 8x8 microtile.
__global__ void __launch_bounds__(256,2) gemm_xg_kernel(const float* __restrict__ X,
                                                        const float* __restrict__ Wf,
                                                        const float* __restrict__ Wb)
{
    __shared__ float As[16][132];
    __shared__ float Bs[16][132];
    int tid = threadIdx.x;
    int tx = tid & 15, ty = tid >> 4;
    int m0 = blockIdx.y * 128;
    int n0 = blockIdx.x * 128;
    float acc[8][8];
#pragma unroll
    for (int i=0;i<8;i++)
#pragma unroll
        for (int j=0;j<8;j++) acc[i][j]=0.f;

    for (int k0=0;k0<DIM;k0+=16){
#pragma unroll
        for (int rep=0;rep<2;rep++){
            int idx = tid + rep*256;
            int r = idx >> 2, q = idx & 3;
            const float4 v = *reinterpret_cast<const float4*>(&X[(size_t)(m0+r)*DIM + k0 + q*4]);
            As[q*4+0][r]=v.x; As[q*4+1][r]=v.y; As[q*4+2][r]=v.z; As[q*4+3][r]=v.w;
        }
#pragma unroll
        for (int rep=0;rep<2;rep++){
            int idx = tid + rep*256;
            int r = idx >> 2, q = idx & 3;
            int n = n0 + r;
            const float* W = (n & 2048) ? Wb : Wf;
            int g = n & 2047;
            const float4 v = *reinterpret_cast<const float4*>(&W[(size_t)g*DIM + k0 + q*4]);
            Bs[q*4+0][r]=v.x; Bs[q*4+1][r]=v.y; Bs[q*4+2][r]=v.z; Bs[q*4+3][r]=v.w;
        }
        __syncthreads();
#pragma unroll
        for (int kk=0;kk<16;kk++){
            float a[8], bb[8];
#pragma unroll
            for (int i=0;i<8;i++) a[i]=As[kk][ty+16*i];
#pragma unroll
            for (int j=0;j<8;j++) bb[j]=Bs[kk][tx+16*j];
#pragma unroll
            for (int i=0;i<8;i++)
#pragma unroll
                for (int j=0;j<8;j++) acc[i][j] = fmaf(a[i], bb[j], acc[i][j]);
        }
        __syncthreads();
    }
#pragma unroll
    for (int i=0;i<8;i++){
        int m = m0 + ty + 16*i;
        int s = m >> 6, b = m & 63;
#pragma unroll
        for (int j=0;j<8;j++){
            int n = n0 + tx + 16*j;
            int dir = n >> 11, g = n & 2047;
            size_t idx = ((((size_t)dir*SLEN) + s)*G4 + g)*BSZ + b;
            d_xg[idx] = acc[i][j] + d_bias[n];
        }
    }
}

// ---------------- one LSTM time step (both directions), 128 blocks ----------------
// block = (dir, chunk of 8 hidden units); computes all 4 gates x 64 batches.
__global__ void __launch_bounds__(128,4) lstm_step_kernel(int tf, int par,
                                  const float* __restrict__ Whf,
                                  const float* __restrict__ Whb)
{
    __shared__ float Ws[32][33];
    __shared__ float Hs[32][64];
    int tid = threadIdx.x;
    int dir = blockIdx.x >> 6;
    int chunk = blockIdx.x & 63;
    int j0 = chunk * 8;
    int t = dir ? (SLEN-1-tf) : tf;
    const float* W = dir ? Whb : Whf;
    const float* hprev = d_hbuf[par] + dir*HID*BSZ;
    float acc[4][4] = {{0.f,0.f,0.f,0.f},{0.f,0.f,0.f,0.f},{0.f,0.f,0.f,0.f},{0.f,0.f,0.f,0.f}};
    int tb = tid & 15, jj = tid >> 4;   // jj in [0,8)

    for (int k0=0;k0<HID;k0+=32){
#pragma unroll
        for (int rep=0;rep<2;rep++){
            int idx = tid + rep*128;
            int r = idx >> 3, q = idx & 7;
            int gate = r >> 3, j = j0 + (r & 7);
            const float4 v = *reinterpret_cast<const float4*>(&W[(size_t)(gate*HID + j)*HID + k0 + q*4]);
            Ws[r][q*4+0]=v.x; Ws[r][q*4+1]=v.y; Ws[r][q*4+2]=v.z; Ws[r][q*4+3]=v.w;
        }
        const float4* hs = reinterpret_cast<const float4*>(hprev + k0*BSZ);
        float4* hd = reinterpret_cast<float4*>(&Hs[0][0]);
#pragma unroll
        for (int rep=0;rep<4;rep++) hd[tid + rep*128] = hs[tid + rep*128];
        __syncthreads();
#pragma unroll
        for (int kk=0;kk<32;kk++){
            float w0=Ws[   jj][kk], w1=Ws[ 8+jj][kk], w2=Ws[16+jj][kk], w3=Ws[24+jj][kk];
#pragma unroll
            for (int bi=0;bi<4;bi++){
                float hv = Hs[kk][tb + 16*bi];
                acc[0][bi]=fmaf(w0,hv,acc[0][bi]);
                acc[1][bi]=fmaf(w1,hv,acc[1][bi]);
                acc[2][bi]=fmaf(w2,hv,acc[2][bi]);
                acc[3][bi]=fmaf(w3,hv,acc[3][bi]);
            }
        }
        __syncthreads();
    }
    int j = j0 + jj;
    size_t xgb = (((size_t)dir*SLEN)+t)*G4*BSZ;
    float* hnext = d_hbuf[par^1] + dir*HID*BSZ;
    const float* cprev = d_cbuf[par] + dir*HID*BSZ;
    float* cnext = d_cbuf[par^1] + dir*HID*BSZ;
#pragma unroll
    for (int bi=0;bi<4;bi++){
        int b = tb + 16*bi;
        float gi = acc[0][bi] + d_xg[xgb + (size_t)(0*HID+j)*BSZ + b];
        float gf = acc[1][bi] + d_xg[xgb + (size_t)(1*HID+j)*BSZ + b];
        float gg = acc[2][bi] + d_xg[xgb + (size_t)(2*HID+j)*BSZ + b];
        float go = acc[3][bi] + d_xg[xgb + (size_t)(3*HID+j)*BSZ + b];
        float ig = sigm(gi), fg = sigm(gf), og = sigm(go);
        float gt = tanhf(gg);
        float co = cprev[j*BSZ + b];
        float cn = fg*co + ig*gt;
        float hn = og * tanhf(cn);
        cnext[j*BSZ+b] = cn;
        hnext[j*BSZ+b] = hn;
        d_hall[(((size_t)t*2 + dir)*HID + j)*BSZ + b] = hn;
    }
}

// ---------------- batchnorm statistics: one block per feature ----------------
__global__ void bn_stats_kernel()
{
    int f = blockIdx.x;          // 0..1023
    int tid = threadIdx.x;       // 256 threads, one s-row each
    const float4* p = reinterpret_cast<const float4*>(&d_hall[((size_t)tid*2*HID + f)*BSZ]);
    float sum=0.f, sq=0.f;
#pragma unroll
    for (int i=0;i<16;i++){
        float4 v = p[i];
        sum += v.x+v.y+v.z+v.w;
        sq  += v.x*v.x + v.y*v.y + v.z*v.z + v.w*v.w;
    }
    __shared__ float ss[256], s2[256];
    ss[tid]=sum; s2[tid]=sq;
    __syncthreads();
    for (int o=128;o>0;o>>=1){
        if (tid<o){ ss[tid]+=ss[tid+o]; s2[tid]+=s2[tid+o]; }
        __syncthreads();
    }
    if (tid==0){
        float mean = ss[0] / (float)NROWS;
        float var  = s2[0] / (float)NROWS - mean*mean;
        d_mean[f] = mean;
        d_rstd[f] = rsqrtf(var + 1e-5f);
    }
}

// ---------------- fold BN into linear: A[t][f], Cc[t] ----------------
__global__ void ac_kernel(const float* __restrict__ gamma, const float* __restrict__ beta,
                          const float* __restrict__ lw, const float* __restrict__ lb)
{
    int t = blockIdx.x, tid = threadIdx.x;   // 17 blocks x 128
    float cs = 0.f;
    for (int f=tid; f<2*HID; f+=128){
        float sc = gamma[f]*d_rstd[f];
        float sh = beta[f] - d_mean[f]*sc;
        float w = lw[t*2*HID + f];
        d_A[t*2*HID + f] = w*sc;
        cs += sh*w;
    }
    __shared__ float red[128];
    red[tid]=cs; __syncthreads();
    for (int o=64;o>0;o>>=1){ if (tid<o) red[tid]+=red[tid+o]; __syncthreads(); }
    if (tid==0) d_Cc[t] = lb[t] + red[0];
}

// ---------------- emissions E[b][s][t] ----------------
__global__ void logits_kernel()
{
    int s = blockIdx.x;
    int b = threadIdx.x;           // 64 threads
    __shared__ float As[NT][256];
    float acc[NT];
#pragma unroll
    for (int t=0;t<NT;t++) acc[t]=0.f;
    for (int f0=0; f0<2*HID; f0+=256){
        for (int idx=b; idx<NT*256; idx+=64){
            int t = idx >> 8, fi = idx & 255;
            As[t][fi] = d_A[t*2*HID + f0 + fi];
        }
        __syncthreads();
        for (int fi=0; fi<256; fi++){
            float hv = d_hall[((size_t)s*2*HID + f0+fi)*BSZ + b];
#pragma unroll
            for (int t=0;t<NT;t++) acc[t] = fmaf(hv, As[t][fi], acc[t]);
        }
        __syncthreads();
    }
#pragma unroll
    for (int t=0;t<NT;t++)
        d_E[((size_t)b*SLEN + s)*NT + t] = acc[t] + d_Cc[t];
}

// ---------------- CRF: numerator, forward logZ, viterbi — one warp per batch ----------------
__global__ void crf_kernel(const int* __restrict__ labels, const float* __restrict__ start,
                           const float* __restrict__ endv, const float* __restrict__ trans,
                           float* __restrict__ out)
{
    int b = blockIdx.x;
    int lane = threadIdx.x;   // 32
    __shared__ float tr[NT*NT];
    __shared__ float alpha[NT], score[NT];
    for (int i=lane;i<NT*NT;i+=32) tr[i]=trans[i];
    __syncwarp();

    // numerator + mask count
    float numpart=0.f; int cnt=0;
    for (int s=lane; s<SLEN; s+=32){
        int m = d_maskI[s*BSZ + b];
        cnt += m;
        int ys = labels[s*BSZ + b];
        float emit = d_E[((size_t)b*SLEN + s)*NT + ys];
        if (s==0) numpart += start[ys] + emit;
        else if (m){
            int yp = labels[(s-1)*BSZ + b];
            numpart += tr[yp*NT + ys] + emit;
        }
    }
    for (int o=16;o>0;o>>=1){
        numpart += __shfl_down_sync(0xffffffffu, numpart, o);
        cnt     += __shfl_down_sync(0xffffffffu, cnt, o);
    }
    float num = 0.f;
    if (lane==0){
        int last = cnt - 1;
        num = numpart + endv[labels[last*BSZ + b]];
    }

    // init
    if (lane < NT){
        float a0 = start[lane] + d_E[((size_t)b*SLEN)*NT + lane];
        alpha[lane] = a0;
        score[lane] = a0;
    }
    __syncwarp();

    for (int s=1;s<SLEN;s++){
        float lse=0.f, best=0.f; int bp=0;
        if (lane < NT){
            float e = d_E[((size_t)b*SLEN + s)*NT + lane];
            float mx = -1e30f;
#pragma unroll
            for (int t1=0;t1<NT;t1++) mx = fmaxf(mx, alpha[t1] + tr[t1*NT + lane]);
            float sm = 0.f;
#pragma unroll
            for (int t1=0;t1<NT;t1++) sm += expf(alpha[t1] + tr[t1*NT + lane] - mx);
            lse = mx + logf(sm) + e;
            float bv = -1e30f;
#pragma unroll
            for (int t1=0;t1<NT;t1++){
                float v = score[t1] + tr[t1*NT + lane];
                if (v > bv){ bv = v; bp = t1; }
            }
            best = bv + e;
            d_bp[((size_t)b*SLEN + s)*NT + lane] = bp;
        }
        __syncwarp();
        if (lane < NT){
            int m = d_maskI[s*BSZ + b];
            if (m){ alpha[lane] = lse; score[lane] = best; }
        }
        __syncwarp();
    }

    // partition function Z
    float av = (lane<NT) ? alpha[lane] + endv[lane] : -1e30f;
    float mx = av;
    for (int o=16;o>0;o>>=1) mx = fmaxf(mx, __shfl_xor_sync(0xffffffffu, mx, o));
    float ex = (lane<NT) ? expf(av - mx) : 0.f;
    for (int o=16;o>0;o>>=1) ex += __shfl_xor_sync(0xffffffffu, ex, o);
    float Z = mx + logf(ex);
    if (lane==0) d_lossParts[b] = Z - num;

    // viterbi backtrack (lane 0)
    if (lane==0){
        float bv=-1e30f; int tag=0;
        for (int t=0;t<NT;t++){
            float v = score[t] + endv[t];
            if (v > bv){ bv=v; tag=t; }
        }
        for (int s=SLEN-1; s>=1; --s){
            int m = d_maskI[s*BSZ + b];
            out[1 + b*SLEN + s] = m ? (float)tag : 0.f;
            tag = m ? d_bp[((size_t)b*SLEN + s)*NT + tag] : tag;
        }
        int m0 = d_maskI[b];
        out[1 + b*SLEN] = m0 ? (float)tag : 0.f;
    }
}

__global__ void loss_reduce_kernel(float* __restrict__ out)
{
    int l = threadIdx.x;   // 32
    float v = d_lossParts[l] + d_lossParts[l+32];
    for (int o=16;o>0;o>>=1) v += __shfl_xor_sync(0xffffffffu, v, o);
    if (l==0) out[0] = v;
}

// ---------------- launch ----------------
extern "C" void kernel_launch(void* const* d_in, const int* in_sizes, int n_in,
                              void* d_out, int out_size)
{
    const float* word   = (const float*)d_in[0];
    const void*  mask   = d_in[1];
    const int*   labels = (const int*)d_in[2];
    const float* w_ih_f = (const float*)d_in[3];
    const float* w_hh_f = (const float*)d_in[4];
    const float* b_ih_f = (const float*)d_in[5];
    const float* b_hh_f = (const float*)d_in[6];
    const float* w_ih_b = (const float*)d_in[7];
    const float* w_hh_b = (const float*)d_in[8];
    const float* b_ih_b = (const float*)d_in[9];
    const float* b_hh_b = (const float*)d_in[10];
    const float* gamma  = (const float*)d_in[11];
    const float* beta   = (const float*)d_in[12];
    const float* lin_w  = (const float*)d_in[13];
    const float* lin_b  = (const float*)d_in[14];
    const float* cstart = (const float*)d_in[15];
    const float* cend   = (const float*)d_in[16];
    const float* ctrans = (const float*)d_in[17];
    float* out = (float*)d_out;

    prep_kernel<<<256,256>>>(b_ih_f,b_hh_f,b_ih_b,b_hh_b, mask);

    dim3 g1(NCOLS/128, NROWS/128);     // (32, 128)
    gemm_xg_kernel<<<g1,256>>>(word, w_ih_f, w_ih_b);

    for (int t=0;t<SLEN;t++)
        lstm_step_kernel<<<128,128>>>(t, t&1, w_hh_f, w_hh_b);

    bn_stats_kernel<<<2*HID,256>>>();
    ac_kernel<<<NT,128>>>(gamma,beta,lin_w,lin_b);
    logits_kernel<<<SLEN,64>>>();
    crf_kernel<<<BSZ,32>>>(labels, cstart, cend, ctrans, out);
    loss_reduce_kernel<<<1,32>>>(out);
}

// round 2
// speedup vs baseline: 1.0612x; 1.0612x over previous
#include <cuda_runtime.h>
#include <math.h>

#define SLEN 256
#define BSZ  64
#define DIM  1024
#define HID  512
#define NT   17
#define G4   (4*HID)    // 2048 gate rows per direction
#define NCOLS (2*G4)    // 4096 combined columns (fwd+bwd)
#define NROWS (SLEN*BSZ)

// ---------------- device scratch (no allocations allowed) ----------------
__device__ float d_xg[(size_t)2*SLEN*G4*BSZ];          // [dir][s][g][b]  256MB
__device__ float d_h[2][2*HID*BSZ];                    // ping-pong [p][dir][j][b]
__device__ float d_c[2*HID*BSZ];                       // [dir][j][b]
__device__ float d_hall[(size_t)SLEN*2*HID*BSZ];       // [s][f=dir*512+j][b] 64MB
__device__ float d_bias[NCOLS];
__device__ float d_mean[2*HID], d_rstd[2*HID];
__device__ float d_A[NT*2*HID];
__device__ float d_Cc[NT];
__device__ float d_E[(size_t)BSZ*SLEN*NT];             // [b][s][t]
__device__ int   d_bp[(size_t)BSZ*SLEN*NT];
__device__ int   d_maskI[SLEN*BSZ];                    // [s][b]
__device__ float d_lossParts[BSZ];
__device__ int   d_barCount;

__device__ __forceinline__ float sigm(float x){ return 1.f/(1.f+expf(-x)); }

__device__ __forceinline__ void fma2(unsigned long long &d, unsigned long long a, unsigned long long b){
    asm volatile("fma.rn.f32x2 %0, %1, %2, %0;" : "+l"(d) : "l"(a), "l"(b));
}

// ---------------- prep: bias fold, mask normalize, h0/c0 zero, barrier reset ----------------
__global__ void prep_kernel(const float* __restrict__ bif, const float* __restrict__ bhf,
                            const float* __restrict__ bib, const float* __restrict__ bhb,
                            const void* __restrict__ maskraw)
{
    int idx = blockIdx.x*blockDim.x + threadIdx.x;     // grid covers 65536
    if (idx == 0) d_barCount = 0;
    if (idx < NCOLS){
        int dir = idx >> 11, g = idx & 2047;
        d_bias[idx] = dir ? (bib[g]+bhb[g]) : (bif[g]+bhf[g]);
    }
    if (idx < SLEN*BSZ){
        const unsigned char* rb = (const unsigned char*)maskraw;
        // mask[0][1] is always true (lengths >= SL/2). bool layout -> byte1==1,
        // int32/float32 layout -> byte1==0.
        bool isbool = (rb[1] != 0);
        int v;
        if (isbool) v = (rb[idx] != 0);
        else        v = (((const int*)maskraw)[idx] != 0);
        d_maskI[idx] = v;
    }
    if (idx < 2*HID*BSZ){
        d_h[0][idx] = 0.f;
        d_c[idx]    = 0.f;
    }
}

// ---------------- big input GEMM: xg[dir][s][g][b] = X@W^T + bias ----------------
// M=16384 (s*64+b), K=1024, N=4096 (dir*2048+g). 128x128 tile, 8x8 microtile.
__global__ void __launch_bounds__(256,2) gemm_xg_kernel(const float* __restrict__ X,
                                                        const float* __restrict__ Wf,
                                                        const float* __restrict__ Wb)
{
    __shared__ float As[16][132];
    __shared__ float Bs[16][132];
    int tid = threadIdx.x;
    int tx = tid & 15, ty = tid >> 4;
    int m0 = blockIdx.y * 128;
    int n0 = blockIdx.x * 128;
    float acc[8][8];
#pragma unroll
    for (int i=0;i<8;i++)
#pragma unroll
        for (int j=0;j<8;j++) acc[i][j]=0.f;

    for (int k0=0;k0<DIM;k0+=16){
#pragma unroll
        for (int rep=0;rep<2;rep++){
            int idx = tid + rep*256;
            int r = idx >> 2, q = idx & 3;
            const float4 v = *reinterpret_cast<const float4*>(&X[(size_t)(m0+r)*DIM + k0 + q*4]);
            As[q*4+0][r]=v.x; As[q*4+1][r]=v.y; As[q*4+2][r]=v.z; As[q*4+3][r]=v.w;
        }
#pragma unroll
        for (int rep=0;rep<2;rep++){
            int idx = tid + rep*256;
            int r = idx >> 2, q = idx & 3;
            int n = n0 + r;
            const float* W = (n & 2048) ? Wb : Wf;
            int g = n & 2047;
            const float4 v = *reinterpret_cast<const float4*>(&W[(size_t)g*DIM + k0 + q*4]);
            Bs[q*4+0][r]=v.x; Bs[q*4+1][r]=v.y; Bs[q*4+2][r]=v.z; Bs[q*4+3][r]=v.w;
        }
        __syncthreads();
#pragma unroll
        for (int kk=0;kk<16;kk++){
            float a[8], bb[8];
#pragma unroll
            for (int i=0;i<8;i++) a[i]=As[kk][ty+16*i];
#pragma unroll
            for (int j=0;j<8;j++) bb[j]=Bs[kk][tx+16*j];
#pragma unroll
            for (int i=0;i<8;i++)
#pragma unroll
                for (int j=0;j<8;j++) acc[i][j] = fmaf(a[i], bb[j], acc[i][j]);
        }
        __syncthreads();
    }
#pragma unroll
    for (int i=0;i<8;i++){
        int m = m0 + ty + 16*i;
        int s = m >> 6, b = m & 63;
#pragma unroll
        for (int j=0;j<8;j++){
            int n = n0 + tx + 16*j;
            int dir = n >> 11, g = n & 2047;
            size_t idx = ((((size_t)dir*SLEN) + s)*G4 + g)*BSZ + b;
            d_xg[idx] = acc[i][j] + d_bias[n];
        }
    }
}

// ---------------- persistent bidirectional LSTM ----------------
// 128 blocks x 128 threads, all co-resident (<=148 SMs, 1 block/SM).
// block = (dir, chunk of 8 hidden units): 32 gate rows x 64 batches per step.
// W_hh slice (32x512) lives in SMEM for all 256 steps. Steps separated by a
// software grid barrier (release/acquire on d_barCount). h ping-pongs in
// global memory, read with __ldcg to bypass (possibly stale) L1.
#define WT_STRIDE 36
#define HS_OFF    (512*WT_STRIDE)          // 18432 floats
#define HS_STRIDE 132
#define GS_STRIDE 34
#define SMEM_FLOATS (HS_OFF + 64*HS_STRIDE)  // 26880 floats = 107520 B

__global__ void __launch_bounds__(128,1) lstm_persist(const float* __restrict__ Whf,
                                                      const float* __restrict__ Whb)
{
    extern __shared__ float sm[];
    const int tid = threadIdx.x;
    const int dir = blockIdx.x >> 6;
    const int chunk = blockIdx.x & 63;
    const int j0 = chunk * 8;
    const int rg = tid & 3;        // gate
    const int bg = tid >> 2;       // batch pair index (0..31)
    const float* W = dir ? Whb : Whf;

    float* Wt = sm;                // [512][36]: Wt[k*36 + r], r = gate*8+jj
    float* Hs = sm + HS_OFF;       // [64][132]: duplicated pairs (h,h) per batch
    float* Gs = Hs;                // reused after FMA: [64 b][34]

    // one-time weight load (coalesced global, scattered SMEM stores)
    for (int idx = tid; idx < 32*512; idx += 128){
        int r = idx >> 9;
        int k = idx & 511;
        int gate = r >> 3, jj = r & 7;
        Wt[k*WT_STRIDE + r] = W[(size_t)(gate*HID + j0 + jj)*HID + k];
    }

    for (int step = 0; step < SLEN; step++){
        int par = step & 1;
        int t = dir ? (SLEN-1-step) : step;
        const float* hprev = &d_h[par][dir*HID*BSZ];

        unsigned long long acc[4][2];
#pragma unroll
        for (int i=0;i<4;i++){ acc[i][0]=0ull; acc[i][1]=0ull; }

        // prefetch first h tile
        float4 st[8];
#pragma unroll
        for (int it=0; it<8; it++){
            int lin = tid + it*128;
            st[it] = __ldcg((const float4*)&hprev[(lin>>4)*64 + ((lin&15)<<2)]);
        }

        for (int tile=0; tile<8; tile++){
            __syncthreads();   // Hs region free (prev FMA / prev Gs use done)
#pragma unroll
            for (int it=0; it<8; it++){
                int lin = tid + it*128;
                int kk = lin >> 4;
                int b4 = (lin & 15) << 2;
                float4 v = st[it];
                float* dst = Hs + kk*HS_STRIDE + 2*b4;
                *(float4*)dst     = make_float4(v.x,v.x,v.y,v.y);
                *(float4*)(dst+4) = make_float4(v.z,v.z,v.w,v.w);
            }
            __syncthreads();
            if (tile < 7){
#pragma unroll
                for (int it=0; it<8; it++){
                    int lin = tid + it*128;
                    st[it] = __ldcg((const float4*)&hprev[((tile+1)*64 + (lin>>4))*64 + ((lin&15)<<2)]);
                }
            }
            const float* wp = Wt + (tile*64)*WT_STRIDE + rg*8;
            const float* hp = Hs + bg*4;
#pragma unroll 16
            for (int kk=0; kk<64; kk++){
                ulonglong2 w01 = *(const ulonglong2*)wp;        // rows (0,1),(2,3)
                ulonglong2 w23 = *(const ulonglong2*)(wp+4);    // rows (4,5),(6,7)
                ulonglong2 hh  = *(const ulonglong2*)hp;        // (hb,hb),(hb1,hb1)
                fma2(acc[0][0], w01.x, hh.x); fma2(acc[0][1], w01.x, hh.y);
                fma2(acc[1][0], w01.y, hh.x); fma2(acc[1][1], w01.y, hh.y);
                fma2(acc[2][0], w23.x, hh.x); fma2(acc[2][1], w23.x, hh.y);
                fma2(acc[3][0], w23.y, hh.x); fma2(acc[3][1], w23.y, hh.y);
                wp += WT_STRIDE; hp += HS_STRIDE;
            }
        }
        __syncthreads();    // all FMA reads of Hs done; Gs can overwrite
#pragma unroll
        for (int rp=0; rp<4; rp++){
#pragma unroll
            for (int bi=0; bi<2; bi++){
                int b = 2*bg + bi;
                float2 f = *reinterpret_cast<float2*>(&acc[rp][bi]); // rows 2rp,2rp+1
                *reinterpret_cast<float2*>(&Gs[b*GS_STRIDE + rg*8 + 2*rp]) = f;
            }
        }
        __syncthreads();

        size_t xgb = (((size_t)dir*SLEN)+t)*G4*BSZ;
        float* hnext = &d_h[par^1][dir*HID*BSZ];
        float* cptr  = &d_c[dir*HID*BSZ];
#pragma unroll
        for (int it=0; it<4; it++){
            int cell = tid + it*128;
            int jj = cell >> 6, b = cell & 63;
            int j = j0 + jj;
            float gi = Gs[b*GS_STRIDE +      jj] + d_xg[xgb + (size_t)(0*HID+j)*BSZ + b];
            float gf = Gs[b*GS_STRIDE +  8 + jj] + d_xg[xgb + (size_t)(1*HID+j)*BSZ + b];
            float gg = Gs[b*GS_STRIDE + 16 + jj] + d_xg[xgb + (size_t)(2*HID+j)*BSZ + b];
            float go = Gs[b*GS_STRIDE + 24 + jj] + d_xg[xgb + (size_t)(3*HID+j)*BSZ + b];
            float ig = sigm(gi), fg = sigm(gf), og = sigm(go);
            float gt = tanhf(gg);
            float co = cptr[j*BSZ + b];
            float cn = fg*co + ig*gt;
            float hn = og * tanhf(cn);
            cptr[j*BSZ+b] = cn;
            hnext[j*BSZ+b] = hn;
            d_hall[(((size_t)t*2 + dir)*HID + j)*BSZ + b] = hn;
        }

        // grid barrier: release increment + acquire poll
        __syncthreads();
        if (tid == 0){
            __threadfence();
            asm volatile("red.release.gpu.add.s32 [%0], %1;" :: "l"(&d_barCount), "r"(1) : "memory");
            int target = 128*(step+1);
            int v;
            do {
                asm volatile("ld.acquire.gpu.s32 %0, [%1];" : "=r"(v) : "l"(&d_barCount) : "memory");
                if (v < target) __nanosleep(32);
            } while (v < target);
        }
        __syncthreads();
    }
}

// ---------------- batchnorm statistics: one block per feature ----------------
__global__ void bn_stats_kernel()
{
    int f = blockIdx.x;          // 0..1023
    int tid = threadIdx.x;       // 256 threads, one s-row each
    const float4* p = reinterpret_cast<const float4*>(&d_hall[((size_t)tid*2*HID + f)*BSZ]);
    float sum=0.f, sq=0.f;
#pragma unroll
    for (int i=0;i<16;i++){
        float4 v = p[i];
        sum += v.x+v.y+v.z+v.w;
        sq  += v.x*v.x + v.y*v.y + v.z*v.z + v.w*v.w;
    }
    __shared__ float ss[256], s2[256];
    ss[tid]=sum; s2[tid]=sq;
    __syncthreads();
    for (int o=128;o>0;o>>=1){
        if (tid<o){ ss[tid]+=ss[tid+o]; s2[tid]+=s2[tid+o]; }
        __syncthreads();
    }
    if (tid==0){
        float mean = ss[0] / (float)NROWS;
        float var  = s2[0] / (float)NROWS - mean*mean;
        d_mean[f] = mean;
        d_rstd[f] = rsqrtf(var + 1e-5f);
    }
}

// ---------------- fold BN into linear: A[t][f], Cc[t] ----------------
__global__ void ac_kernel(const float* __restrict__ gamma, const float* __restrict__ beta,
                          const float* __restrict__ lw, const float* __restrict__ lb)
{
    int t = blockIdx.x, tid = threadIdx.x;   // 17 blocks x 128
    float cs = 0.f;
    for (int f=tid; f<2*HID; f+=128){
        float sc = gamma[f]*d_rstd[f];
        float sh = beta[f] - d_mean[f]*sc;
        float w = lw[t*2*HID + f];
        d_A[t*2*HID + f] = w*sc;
        cs += sh*w;
    }
    __shared__ float red[128];
    red[tid]=cs; __syncthreads();
    for (int o=64;o>0;o>>=1){ if (tid<o) red[tid]+=red[tid+o]; __syncthreads(); }
    if (tid==0) d_Cc[t] = lb[t] + red[0];
}

// ---------------- emissions E[b][s][t] ----------------
__global__ void logits_kernel()
{
    int s = blockIdx.x;
    int b = threadIdx.x;           // 64 threads
    __shared__ float As[NT][256];
    float acc[NT];
#pragma unroll
    for (int t=0;t<NT;t++) acc[t]=0.f;
    for (int f0=0; f0<2*HID; f0+=256){
        for (int idx=b; idx<NT*256; idx+=64){
            int t = idx >> 8, fi = idx & 255;
            As[t][fi] = d_A[t*2*HID + f0 + fi];
        }
        __syncthreads();
        for (int fi=0; fi<256; fi++){
            float hv = d_hall[((size_t)s*2*HID + f0+fi)*BSZ + b];
#pragma unroll
            for (int t=0;t<NT;t++) acc[t] = fmaf(hv, As[t][fi], acc[t]);
        }
        __syncthreads();
    }
#pragma unroll
    for (int t=0;t<NT;t++)
        d_E[((size_t)b*SLEN + s)*NT + t] = acc[t] + d_Cc[t];
}

// ---------------- CRF: numerator, forward logZ, viterbi — one warp per batch ----------------
__global__ void crf_kernel(const int* __restrict__ labels, const float* __restrict__ start,
                           const float* __restrict__ endv, const float* __restrict__ trans,
                           float* __restrict__ out)
{
    int b = blockIdx.x;
    int lane = threadIdx.x;   // 32
    __shared__ float tr[NT*NT];
    __shared__ float alpha[NT], score[NT];
    for (int i=lane;i<NT*NT;i+=32) tr[i]=trans[i];
    __syncwarp();

    // numerator + mask count
    float numpart=0.f; int cnt=0;
    for (int s=lane; s<SLEN; s+=32){
        int m = d_maskI[s*BSZ + b];
        cnt += m;
        int ys = labels[s*BSZ + b];
        float emit = d_E[((size_t)b*SLEN + s)*NT + ys];
        if (s==0) numpart += start[ys] + emit;
        else if (m){
            int yp = labels[(s-1)*BSZ + b];
            numpart += tr[yp*NT + ys] + emit;
        }
    }
    for (int o=16;o>0;o>>=1){
        numpart += __shfl_down_sync(0xffffffffu, numpart, o);
        cnt     += __shfl_down_sync(0xffffffffu, cnt, o);
    }
    float num = 0.f;
    if (lane==0){
        int last = cnt - 1;
        num = numpart + endv[labels[last*BSZ + b]];
    }

    // init
    if (lane < NT){
        float a0 = start[lane] + d_E[((size_t)b*SLEN)*NT + lane];
        alpha[lane] = a0;
        score[lane] = a0;
    }
    __syncwarp();

    for (int s=1;s<SLEN;s++){
        float lse=0.f, best=0.f; int bp=0;
        if (lane < NT){
            float e = d_E[((size_t)b*SLEN + s)*NT + lane];
            float mx = -1e30f;
#pragma unroll
            for (int t1=0;t1<NT;t1++) mx = fmaxf(mx, alpha[t1] + tr[t1*NT + lane]);
            float sm = 0.f;
#pragma unroll
            for (int t1=0;t1<NT;t1++) sm += expf(alpha[t1] + tr[t1*NT + lane] - mx);
            lse = mx + logf(sm) + e;
            float bv = -1e30f;
#pragma unroll
            for (int t1=0;t1<NT;t1++){
                float v = score[t1] + tr[t1*NT + lane];
                if (v > bv){ bv = v; bp = t1; }
            }
            best = bv + e;
            d_bp[((size_t)b*SLEN + s)*NT + lane] = bp;
        }
        __syncwarp();
        if (lane < NT){
            int m = d_maskI[s*BSZ + b];
            if (m){ alpha[lane] = lse; score[lane] = best; }
        }
        __syncwarp();
    }

    // partition function Z
    float av = (lane<NT) ? alpha[lane] + endv[lane] : -1e30f;
    float mx = av;
    for (int o=16;o>0;o>>=1) mx = fmaxf(mx, __shfl_xor_sync(0xffffffffu, mx, o));
    float ex = (lane<NT) ? expf(av - mx) : 0.f;
    for (int o=16;o>0;o>>=1) ex += __shfl_xor_sync(0xffffffffu, ex, o);
    float Z = mx + logf(ex);
    if (lane==0) d_lossParts[b] = Z - num;

    // viterbi backtrack (lane 0)
    if (lane==0){
        float bv=-1e30f; int tag=0;
        for (int t=0;t<NT;t++){
            float v = score[t] + endv[t];
            if (v > bv){ bv=v; tag=t; }
        }
        for (int s=SLEN-1; s>=1; --s){
            int m = d_maskI[s*BSZ + b];
            out[1 + b*SLEN + s] = m ? (float)tag : 0.f;
            tag = m ? d_bp[((size_t)b*SLEN + s)*NT + tag] : tag;
        }
        int m0 = d_maskI[b];
        out[1 + b*SLEN] = m0 ? (float)tag : 0.f;
    }
}

__global__ void loss_reduce_kernel(float* __restrict__ out)
{
    int l = threadIdx.x;   // 32
    float v = d_lossParts[l] + d_lossParts[l+32];
    for (int o=16;o>0;o>>=1) v += __shfl_xor_sync(0xffffffffu, v, o);
    if (l==0) out[0] = v;
}

// ---------------- launch ----------------
extern "C" void kernel_launch(void* const* d_in, const int* in_sizes, int n_in,
                              void* d_out, int out_size)
{
    const float* word   = (const float*)d_in[0];
    const void*  mask   = d_in[1];
    const int*   labels = (const int*)d_in[2];
    const float* w_ih_f = (const float*)d_in[3];
    const float* w_hh_f = (const float*)d_in[4];
    const float* b_ih_f = (const float*)d_in[5];
    const float* b_hh_f = (const float*)d_in[6];
    const float* w_ih_b = (const float*)d_in[7];
    const float* w_hh_b = (const float*)d_in[8];
    const float* b_ih_b = (const float*)d_in[9];
    const float* b_hh_b = (const float*)d_in[10];
    const float* gamma  = (const float*)d_in[11];
    const float* beta   = (const float*)d_in[12];
    const float* lin_w  = (const float*)d_in[13];
    const float* lin_b  = (const float*)d_in[14];
    const float* cstart = (const float*)d_in[15];
    const float* cend   = (const float*)d_in[16];
    const float* ctrans = (const float*)d_in[17];
    float* out = (float*)d_out;

    prep_kernel<<<256,256>>>(b_ih_f,b_hh_f,b_ih_b,b_hh_b, mask);

    dim3 g1(NCOLS/128, NROWS/128);     // (32, 128)
    gemm_xg_kernel<<<g1,256>>>(word, w_ih_f, w_ih_b);

    cudaFuncSetAttribute(lstm_persist, cudaFuncAttributeMaxDynamicSharedMemorySize,
                         SMEM_FLOATS*4);
    lstm_persist<<<128,128,SMEM_FLOATS*4>>>(w_hh_f, w_hh_b);

    bn_stats_kernel<<<2*HID,256>>>();
    ac_kernel<<<NT,128>>>(gamma,beta,lin_w,lin_b);
    logits_kernel<<<SLEN,64>>>();
    crf_kernel<<<BSZ,32>>>(labels, cstart, cend, ctrans, out);
    loss_reduce_kernel<<<1,32>>>(out);
}

// round 3
// speedup vs baseline: 1.2598x; 1.1871x over previous
#include <cuda_runtime.h>
#include <math.h>

#define SLEN 256
#define BSZ  64
#define DIM  1024
#define HID  512
#define NT   17
#define G4   (4*HID)    // 2048 gate rows per direction
#define NCOLS (2*G4)    // 4096 combined columns (fwd+bwd)
#define NROWS (SLEN*BSZ)

// ---------------- device scratch (no allocations allowed) ----------------
__device__ float d_xg[(size_t)2*SLEN*G4*BSZ];          // [dir][s][g][b]  256MB
__device__ float d_h0[2*HID*BSZ];                      // zero initial h
__device__ float d_hall[(size_t)SLEN*2*HID*BSZ];       // [t][f=dir*512+j][b] 64MB
__device__ float d_bias[NCOLS];
__device__ float d_mean[2*HID], d_rstd[2*HID];
__device__ float d_A[NT*2*HID];
__device__ float d_Cc[NT];
__device__ float d_E[(size_t)BSZ*SLEN*NT];             // [b][s][t]
__device__ int   d_bp[(size_t)BSZ*SLEN*NT];
__device__ int   d_maskI[SLEN*BSZ];                    // [s][b]
__device__ float d_lossParts[BSZ];
__device__ int   d_barCount;

__device__ __forceinline__ float sigm(float x){ return 1.f/(1.f+expf(-x)); }

__device__ __forceinline__ void fma2(unsigned long long &d, unsigned long long a, unsigned long long b){
    asm("fma.rn.f32x2 %0, %1, %2, %0;" : "+l"(d) : "l"(a), "l"(b));
}
__device__ __forceinline__ unsigned long long dup2(float a){
    unsigned long long r;
    asm("mov.b64 %0, {%1,%1};" : "=l"(r) : "f"(a));
    return r;
}

// ---------------- prep: bias fold, mask normalize, h0 zero, barrier reset ----------------
__global__ void prep_kernel(const float* __restrict__ bif, const float* __restrict__ bhf,
                            const float* __restrict__ bib, const float* __restrict__ bhb,
                            const void* __restrict__ maskraw)
{
    int idx = blockIdx.x*blockDim.x + threadIdx.x;     // grid covers 65536
    if (idx == 0) d_barCount = 0;
    if (idx < NCOLS){
        int dir = idx >> 11, g = idx & 2047;
        d_bias[idx] = dir ? (bib[g]+bhb[g]) : (bif[g]+bhf[g]);
    }
    if (idx < SLEN*BSZ){
        const unsigned char* rb = (const unsigned char*)maskraw;
        bool isbool = (rb[1] != 0);
        int v;
        if (isbool) v = (rb[idx] != 0);
        else        v = (((const int*)maskraw)[idx] != 0);
        d_maskI[idx] = v;
    }
    if (idx < 2*HID*BSZ) d_h0[idx] = 0.f;
}

// ---------------- big input GEMM: xg[dir][s][g][b] = X@W^T + bias ----------------
// M=16384 (s*64+b), K=1024, N=4096. 128x128 tile; thread microtile 4m x 16n,
// FFMA2 on n-pairs. txm = tid&31 (m fast, coalesced stores), tyn = tid>>5.
__global__ void __launch_bounds__(256,2) gemm_xg_kernel(const float* __restrict__ X,
                                                        const float* __restrict__ Wf,
                                                        const float* __restrict__ Wb)
{
    __shared__ float As[16][132];
    __shared__ float Bs[16][132];
    int tid = threadIdx.x;
    int txm = tid & 31, tyn = tid >> 5;      // m-lane, n-group
    int m0 = blockIdx.y * 128;
    int n0 = blockIdx.x * 128;
    unsigned long long acc[4][8];
#pragma unroll
    for (int i=0;i<4;i++)
#pragma unroll
        for (int j=0;j<8;j++) acc[i][j]=0ull;

    for (int k0=0;k0<DIM;k0+=16){
#pragma unroll
        for (int rep=0;rep<2;rep++){
            int idx = tid + rep*256;
            int r = idx >> 2, q = idx & 3;
            const float4 v = *reinterpret_cast<const float4*>(&X[(size_t)(m0+r)*DIM + k0 + q*4]);
            As[q*4+0][r]=v.x; As[q*4+1][r]=v.y; As[q*4+2][r]=v.z; As[q*4+3][r]=v.w;
        }
#pragma unroll
        for (int rep=0;rep<2;rep++){
            int idx = tid + rep*256;
            int r = idx >> 2, q = idx & 3;
            int n = n0 + r;
            const float* W = (n & 2048) ? Wb : Wf;
            int g = n & 2047;
            const float4 v = *reinterpret_cast<const float4*>(&W[(size_t)g*DIM + k0 + q*4]);
            Bs[q*4+0][r]=v.x; Bs[q*4+1][r]=v.y; Bs[q*4+2][r]=v.z; Bs[q*4+3][r]=v.w;
        }
        __syncthreads();
#pragma unroll
        for (int kk=0;kk<16;kk++){
            // 16 n values (8 pairs) for this thread: n = tyn*16 + 0..15
            const ulonglong2 b0 = *reinterpret_cast<const ulonglong2*>(&Bs[kk][tyn*16]);
            const ulonglong2 b1 = *reinterpret_cast<const ulonglong2*>(&Bs[kk][tyn*16+4]);
            const ulonglong2 b2 = *reinterpret_cast<const ulonglong2*>(&Bs[kk][tyn*16+8]);
            const ulonglong2 b3 = *reinterpret_cast<const ulonglong2*>(&Bs[kk][tyn*16+12]);
#pragma unroll
            for (int i=0;i<4;i++){
                unsigned long long ad = dup2(As[kk][txm + 32*i]);
                fma2(acc[i][0], ad, b0.x); fma2(acc[i][1], ad, b0.y);
                fma2(acc[i][2], ad, b1.x); fma2(acc[i][3], ad, b1.y);
                fma2(acc[i][4], ad, b2.x); fma2(acc[i][5], ad, b2.y);
                fma2(acc[i][6], ad, b3.x); fma2(acc[i][7], ad, b3.y);
            }
        }
        __syncthreads();
    }
    // store: for fixed (i,jp,half) warp lanes txm cover 32 consecutive b -> 128B coalesced
#pragma unroll
    for (int i=0;i<4;i++){
        int m = m0 + txm + 32*i;
        int s = m >> 6, b = m & 63;
#pragma unroll
        for (int jp=0;jp<8;jp++){
            float2 v = *reinterpret_cast<float2*>(&acc[i][jp]);
            int n = n0 + tyn*16 + 2*jp;
            int dir = n >> 11, g = n & 2047;
            size_t base = ((((size_t)dir*SLEN) + s)*G4 + g)*BSZ + b;
            d_xg[base]       = v.x + d_bias[n];
            d_xg[base + BSZ] = v.y + d_bias[n+1];
        }
    }
}

// ---------------- persistent bidirectional LSTM ----------------
// 128 blocks x 256 threads, all co-resident. block = (dir, chunk of 8 hidden):
// 32 gate rows x 64 batches per step. W_hh slice (32x512) in SMEM for all steps.
// c-state lives in registers. h read straight from d_hall (L2 via __ldcg).
#define WT_STRIDE 36
#define HS_OFF    (512*WT_STRIDE)          // 18432 floats
#define HS_STRIDE 132
#define GS_STRIDE 34
#define SMEM_FLOATS (HS_OFF + 64*HS_STRIDE)  // 26880 floats = 107520 B

__global__ void __launch_bounds__(256,1) lstm_persist(const float* __restrict__ Whf,
                                                      const float* __restrict__ Whb)
{
    extern __shared__ float sm[];
    const int tid = threadIdx.x;
    const int dir = blockIdx.x >> 6;
    const int chunk = blockIdx.x & 63;
    const int j0 = chunk * 8;
    const int q  = tid & 7;       // row quad: rows 4q..4q+3 (of 32)
    const int b2 = tid >> 3;      // batch pair: batches 2b2, 2b2+1
    const float* W = dir ? Whb : Whf;

    float* Wt = sm;                // [512][36]: Wt[k*36 + r], r = gate*8+jj
    float* Hs = sm + HS_OFF;       // [64][132]: duplicated (h,h) pairs per batch
    float* Gs = Hs;                // reused after FMA: [64 b][34]

    for (int idx = tid; idx < 32*512; idx += 256){
        int r = idx >> 9;
        int k = idx & 511;
        int gate = r >> 3, jj = r & 7;
        Wt[k*WT_STRIDE + r] = W[(size_t)(gate*HID + j0 + jj)*HID + k];
    }

    float creg[2] = {0.f, 0.f};

    for (int step = 0; step < SLEN; step++){
        int t = dir ? (SLEN-1-step) : step;

        // prefetch this step's xg contributions into registers (hidden under FMA)
        float xv[2][4];
        {
            size_t xgb = (((size_t)dir*SLEN)+t)*G4*BSZ;
#pragma unroll
            for (int it=0; it<2; it++){
                int cell = tid + it*256;
                int jj = cell >> 6, b = cell & 63;
                int j = j0 + jj;
#pragma unroll
                for (int g=0; g<4; g++)
                    xv[it][g] = __ldg(&d_xg[xgb + (size_t)(g*HID+j)*BSZ + b]);
            }
        }

        unsigned long long acc[2][2] = {{0ull,0ull},{0ull,0ull}};

        if (step > 0){
            int tprev = dir ? (t+1) : (t-1);
            const float* hprev = d_hall + (((size_t)tprev*2 + dir)*HID)*BSZ;

            float4 st[4];
#pragma unroll
            for (int it=0; it<4; it++){
                int lin = tid + it*256;
                st[it] = __ldcg((const float4*)&hprev[(lin>>4)*64 + ((lin&15)<<2)]);
            }
            for (int tile=0; tile<8; tile++){
                __syncthreads();
#pragma unroll
                for (int it=0; it<4; it++){
                    int lin = tid + it*256;
                    int kk = lin >> 4;
                    int b4 = (lin & 15) << 2;
                    float4 v = st[it];
                    float* dst = Hs + kk*HS_STRIDE + 2*b4;
                    *(float4*)dst     = make_float4(v.x,v.x,v.y,v.y);
                    *(float4*)(dst+4) = make_float4(v.z,v.z,v.w,v.w);
                }
                __syncthreads();
                if (tile < 7){
#pragma unroll
                    for (int it=0; it<4; it++){
                        int lin = tid + it*256;
                        st[it] = __ldcg((const float4*)&hprev[((tile+1)*64 + (lin>>4))*64 + ((lin&15)<<2)]);
                    }
                }
                const float* wp = Wt + (tile*64)*WT_STRIDE + q*4;
                const float* hp = Hs + b2*4;
#pragma unroll 16
                for (int kk=0; kk<64; kk++){
                    ulonglong2 w = *(const ulonglong2*)wp;   // rows (4q,4q+1),(4q+2,4q+3)
                    ulonglong2 h = *(const ulonglong2*)hp;   // (hb0,hb0),(hb1,hb1)
                    fma2(acc[0][0], w.x, h.x); fma2(acc[0][1], w.x, h.y);
                    fma2(acc[1][0], w.y, h.x); fma2(acc[1][1], w.y, h.y);
                    wp += WT_STRIDE; hp += HS_STRIDE;
                }
            }
        }
        __syncthreads();    // Hs reads done; Gs may overwrite
#pragma unroll
        for (int i=0;i<2;i++)
#pragma unroll
            for (int j=0;j<2;j++)
                *reinterpret_cast<float2*>(&Gs[(2*b2+j)*GS_STRIDE + 4*q + 2*i]) =
                    *reinterpret_cast<float2*>(&acc[i][j]);
        __syncthreads();

#pragma unroll
        for (int it=0; it<2; it++){
            int cell = tid + it*256;
            int jj = cell >> 6, b = cell & 63;
            int j = j0 + jj;
            float gi = Gs[b*GS_STRIDE +      jj] + xv[it][0];
            float gf = Gs[b*GS_STRIDE +  8 + jj] + xv[it][1];
            float gg = Gs[b*GS_STRIDE + 16 + jj] + xv[it][2];
            float go = Gs[b*GS_STRIDE + 24 + jj] + xv[it][3];
            float ig = sigm(gi), fg = sigm(gf), og = sigm(go);
            float gt = tanhf(gg);
            float cn = fg*creg[it] + ig*gt;
            float hn = og * tanhf(cn);
            creg[it] = cn;
            d_hall[(((size_t)t*2 + dir)*HID + j)*BSZ + b] = hn;
        }

        // grid barrier: release increment + acquire poll
        __syncthreads();
        if (tid == 0){
            __threadfence();
            asm volatile("red.release.gpu.add.s32 [%0], %1;" :: "l"(&d_barCount), "r"(1) : "memory");
            int target = 128*(step+1);
            int v;
            do {
                asm volatile("ld.acquire.gpu.s32 %0, [%1];" : "=r"(v) : "l"(&d_barCount) : "memory");
            } while (v < target);
        }
        __syncthreads();
    }
}

// ---------------- batchnorm statistics: one block per feature ----------------
__global__ void bn_stats_kernel()
{
    int f = blockIdx.x;          // 0..1023
    int tid = threadIdx.x;       // 256 threads, one s-row each
    const float4* p = reinterpret_cast<const float4*>(&d_hall[((size_t)tid*2*HID + f)*BSZ]);
    float sum=0.f, sq=0.f;
#pragma unroll
    for (int i=0;i<16;i++){
        float4 v = p[i];
        sum += v.x+v.y+v.z+v.w;
        sq  += v.x*v.x + v.y*v.y + v.z*v.z + v.w*v.w;
    }
    __shared__ float ss[256], s2[256];
    ss[tid]=sum; s2[tid]=sq;
    __syncthreads();
    for (int o=128;o>0;o>>=1){
        if (tid<o){ ss[tid]+=ss[tid+o]; s2[tid]+=s2[tid+o]; }
        __syncthreads();
    }
    if (tid==0){
        float mean = ss[0] / (float)NROWS;
        float var  = s2[0] / (float)NROWS - mean*mean;
        d_mean[f] = mean;
        d_rstd[f] = rsqrtf(var + 1e-5f);
    }
}

// ---------------- fold BN into linear: A[t][f], Cc[t] ----------------
__global__ void ac_kernel(const float* __restrict__ gamma, const float* __restrict__ beta,
                          const float* __restrict__ lw, const float* __restrict__ lb)
{
    int t = blockIdx.x, tid = threadIdx.x;   // 17 blocks x 128
    float cs = 0.f;
    for (int f=tid; f<2*HID; f+=128){
        float sc = gamma[f]*d_rstd[f];
        float sh = beta[f] - d_mean[f]*sc;
        float w = lw[t*2*HID + f];
        d_A[t*2*HID + f] = w*sc;
        cs += sh*w;
    }
    __shared__ float red[128];
    red[tid]=cs; __syncthreads();
    for (int o=64;o>0;o>>=1){ if (tid<o) red[tid]+=red[tid+o]; __syncthreads(); }
    if (tid==0) d_Cc[t] = lb[t] + red[0];
}

// ---------------- emissions E[b][s][t] ----------------
__global__ void logits_kernel()
{
    int s = blockIdx.x;
    int b = threadIdx.x;           // 64 threads
    __shared__ float As[NT][256];
    float acc[NT];
#pragma unroll
    for (int t=0;t<NT;t++) acc[t]=0.f;
    for (int f0=0; f0<2*HID; f0+=256){
        for (int idx=b; idx<NT*256; idx+=64){
            int t = idx >> 8, fi = idx & 255;
            As[t][fi] = d_A[t*2*HID + f0 + fi];
        }
        __syncthreads();
        for (int fi=0; fi<256; fi++){
            float hv = d_hall[((size_t)s*2*HID + f0+fi)*BSZ + b];
#pragma unroll
            for (int t=0;t<NT;t++) acc[t] = fmaf(hv, As[t][fi], acc[t]);
        }
        __syncthreads();
    }
#pragma unroll
    for (int t=0;t<NT;t++)
        d_E[((size_t)b*SLEN + s)*NT + t] = acc[t] + d_Cc[t];
}

// ---------------- CRF: numerator, forward logZ, viterbi — one warp per batch ----------------
__global__ void crf_kernel(const int* __restrict__ labels, const float* __restrict__ start,
                           const float* __restrict__ endv, const float* __restrict__ trans,
                           float* __restrict__ out)
{
    int b = blockIdx.x;
    int lane = threadIdx.x;   // 32
    __shared__ float tr[NT*NT];
    __shared__ float alpha[NT], score[NT];
    for (int i=lane;i<NT*NT;i+=32) tr[i]=trans[i];
    __syncwarp();

    float numpart=0.f; int cnt=0;
    for (int s=lane; s<SLEN; s+=32){
        int m = d_maskI[s*BSZ + b];
        cnt += m;
        int ys = labels[s*BSZ + b];
        float emit = d_E[((size_t)b*SLEN + s)*NT + ys];
        if (s==0) numpart += start[ys] + emit;
        else if (m){
            int yp = labels[(s-1)*BSZ + b];
            numpart += tr[yp*NT + ys] + emit;
        }
    }
    for (int o=16;o>0;o>>=1){
        numpart += __shfl_down_sync(0xffffffffu, numpart, o);
        cnt     += __shfl_down_sync(0xffffffffu, cnt, o);
    }
    float num = 0.f;
    if (lane==0){
        int last = cnt - 1;
        num = numpart + endv[labels[last*BSZ + b]];
    }

    if (lane < NT){
        float a0 = start[lane] + d_E[((size_t)b*SLEN)*NT + lane];
        alpha[lane] = a0;
        score[lane] = a0;
    }
    __syncwarp();

    for (int s=1;s<SLEN;s++){
        float lse=0.f, best=0.f; int bp=0;
        if (lane < NT){
            float e = d_E[((size_t)b*SLEN + s)*NT + lane];
            float mx = -1e30f;
#pragma unroll
            for (int t1=0;t1<NT;t1++) mx = fmaxf(mx, alpha[t1] + tr[t1*NT + lane]);
            float sm = 0.f;
#pragma unroll
            for (int t1=0;t1<NT;t1++) sm += expf(alpha[t1] + tr[t1*NT + lane] - mx);
            lse = mx + logf(sm) + e;
            float bv = -1e30f;
#pragma unroll
            for (int t1=0;t1<NT;t1++){
                float v = score[t1] + tr[t1*NT + lane];
                if (v > bv){ bv = v; bp = t1; }
            }
            best = bv + e;
            d_bp[((size_t)b*SLEN + s)*NT + lane] = bp;
        }
        __syncwarp();
        if (lane < NT){
            int m = d_maskI[s*BSZ + b];
            if (m){ alpha[lane] = lse; score[lane] = best; }
        }
        __syncwarp();
    }

    float av = (lane<NT) ? alpha[lane] + endv[lane] : -1e30f;
    float mx = av;
    for (int o=16;o>0;o>>=1) mx = fmaxf(mx, __shfl_xor_sync(0xffffffffu, mx, o));
    float ex = (lane<NT) ? expf(av - mx) : 0.f;
    for (int o=16;o>0;o>>=1) ex += __shfl_xor_sync(0xffffffffu, ex, o);
    float Z = mx + logf(ex);
    if (lane==0) d_lossParts[b] = Z - num;

    if (lane==0){
        float bv=-1e30f; int tag=0;
        for (int t=0;t<NT;t++){
            float v = score[t] + endv[t];
            if (v > bv){ bv=v; tag=t; }
        }
        for (int s=SLEN-1; s>=1; --s){
            int m = d_maskI[s*BSZ + b];
            out[1 + b*SLEN + s] = m ? (float)tag : 0.f;
            tag = m ? d_bp[((size_t)b*SLEN + s)*NT + tag] : tag;
        }
        int m0 = d_maskI[b];
        out[1 + b*SLEN] = m0 ? (float)tag : 0.f;
    }
}

__global__ void loss_reduce_kernel(float* __restrict__ out)
{
    int l = threadIdx.x;   // 32
    float v = d_lossParts[l] + d_lossParts[l+32];
    for (int o=16;o>0;o>>=1) v += __shfl_xor_sync(0xffffffffu, v, o);
    if (l==0) out[0] = v;
}

// ---------------- launch ----------------
extern "C" void kernel_launch(void* const* d_in, const int* in_sizes, int n_in,
                              void* d_out, int out_size)
{
    const float* word   = (const float*)d_in[0];
    const void*  mask   = d_in[1];
    const int*   labels = (const int*)d_in[2];
    const float* w_ih_f = (const float*)d_in[3];
    const float* w_hh_f = (const float*)d_in[4];
    const float* b_ih_f = (const float*)d_in[5];
    const float* b_hh_f = (const float*)d_in[6];
    const float* w_ih_b = (const float*)d_in[7];
    const float* w_hh_b = (const float*)d_in[8];
    const float* b_ih_b = (const float*)d_in[9];
    const float* b_hh_b = (const float*)d_in[10];
    const float* gamma  = (const float*)d_in[11];
    const float* beta   = (const float*)d_in[12];
    const float* lin_w  = (const float*)d_in[13];
    const float* lin_b  = (const float*)d_in[14];
    const float* cstart = (const float*)d_in[15];
    const float* cend   = (const float*)d_in[16];
    const float* ctrans = (const float*)d_in[17];
    float* out = (float*)d_out;

    prep_kernel<<<256,256>>>(b_ih_f,b_hh_f,b_ih_b,b_hh_b, mask);

    dim3 g1(NCOLS/128, NROWS/128);     // (32, 128)
    gemm_xg_kernel<<<g1,256>>>(word, w_ih_f, w_ih_b);

    cudaFuncSetAttribute(lstm_persist, cudaFuncAttributeMaxDynamicSharedMemorySize,
                         SMEM_FLOATS*4);
    lstm_persist<<<128,256,SMEM_FLOATS*4>>>(w_hh_f, w_hh_b);

    bn_stats_kernel<<<2*HID,256>>>();
    ac_kernel<<<NT,128>>>(gamma,beta,lin_w,lin_b);
    logits_kernel<<<SLEN,64>>>();
    crf_kernel<<<BSZ,32>>>(labels, cstart, cend, ctrans, out);
    loss_reduce_kernel<<<1,32>>>(out);
}

// round 4
// speedup vs baseline: 1.3503x; 1.0718x over previous
#include <cuda_runtime.h>
#include <math.h>

#define SLEN 256
#define BSZ  64
#define DIM  1024
#define HID  512
#define NT   17
#define G4   (4*HID)    // 2048 gate rows per direction
#define NCOLS (2*G4)    // 4096 combined columns (fwd+bwd)
#define NROWS (SLEN*BSZ)

// ---------------- device scratch (no allocations allowed) ----------------
__device__ float d_xg[(size_t)2*SLEN*G4*BSZ];          // [dir][s][g][b]  256MB
__device__ float d_hall[(size_t)SLEN*2*HID*BSZ];       // [t][f=dir*512+j][b] 64MB
__device__ float d_bias[NCOLS];
__device__ float d_mean[2*HID], d_rstd[2*HID];
__device__ float d_A[NT*2*HID];
__device__ float d_Cc[NT];
__device__ float d_E[(size_t)BSZ*SLEN*NT];             // [b][s][t]
__device__ int   d_bp[(size_t)BSZ*SLEN*NT];
__device__ int   d_maskI[SLEN*BSZ];                    // [s][b]
__device__ float d_lossParts[BSZ];
__device__ int   d_barCount;

__device__ __forceinline__ float sigm(float x){ return 1.f/(1.f+expf(-x)); }

__device__ __forceinline__ void fma2(unsigned long long &d, unsigned long long a, unsigned long long b){
    asm("fma.rn.f32x2 %0, %1, %2, %0;" : "+l"(d) : "l"(a), "l"(b));
}
__device__ __forceinline__ unsigned long long dup2(float a){
    unsigned long long r;
    asm("mov.b64 %0, {%1,%1};" : "=l"(r) : "f"(a));
    return r;
}

// ---------------- prep: bias fold, mask normalize, barrier reset ----------------
__global__ void prep_kernel(const float* __restrict__ bif, const float* __restrict__ bhf,
                            const float* __restrict__ bib, const float* __restrict__ bhb,
                            const void* __restrict__ maskraw)
{
    int idx = blockIdx.x*blockDim.x + threadIdx.x;     // grid covers 65536
    if (idx == 0) d_barCount = 0;
    if (idx < NCOLS){
        int dir = idx >> 11, g = idx & 2047;
        d_bias[idx] = dir ? (bib[g]+bhb[g]) : (bif[g]+bhf[g]);
    }
    if (idx < SLEN*BSZ){
        const unsigned char* rb = (const unsigned char*)maskraw;
        bool isbool = (rb[1] != 0);
        int v;
        if (isbool) v = (rb[idx] != 0);
        else        v = (((const int*)maskraw)[idx] != 0);
        d_maskI[idx] = v;
    }
}

// ---------------- big input GEMM: xg[dir][s][g][b] = X@W^T + bias ----------------
// M=16384 (s*64+b), K=1024, N=4096. 128x128 tile; thread microtile 4m x 16n.
__global__ void __launch_bounds__(256,2) gemm_xg_kernel(const float* __restrict__ X,
                                                        const float* __restrict__ Wf,
                                                        const float* __restrict__ Wb)
{
    __shared__ float As[16][132];
    __shared__ float Bs[16][132];
    int tid = threadIdx.x;
    int txm = tid & 31, tyn = tid >> 5;      // m-lane, n-group
    int m0 = blockIdx.y * 128;
    int n0 = blockIdx.x * 128;
    unsigned long long acc[4][8];
#pragma unroll
    for (int i=0;i<4;i++)
#pragma unroll
        for (int j=0;j<8;j++) acc[i][j]=0ull;

    for (int k0=0;k0<DIM;k0+=16){
#pragma unroll
        for (int rep=0;rep<2;rep++){
            int idx = tid + rep*256;
            int r = idx >> 2, q = idx & 3;
            const float4 v = *reinterpret_cast<const float4*>(&X[(size_t)(m0+r)*DIM + k0 + q*4]);
            As[q*4+0][r]=v.x; As[q*4+1][r]=v.y; As[q*4+2][r]=v.z; As[q*4+3][r]=v.w;
        }
#pragma unroll
        for (int rep=0;rep<2;rep++){
            int idx = tid + rep*256;
            int r = idx >> 2, q = idx & 3;
            int n = n0 + r;
            const float* W = (n & 2048) ? Wb : Wf;
            int g = n & 2047;
            const float4 v = *reinterpret_cast<const float4*>(&W[(size_t)g*DIM + k0 + q*4]);
            Bs[q*4+0][r]=v.x; Bs[q*4+1][r]=v.y; Bs[q*4+2][r]=v.z; Bs[q*4+3][r]=v.w;
        }
        __syncthreads();
#pragma unroll
        for (int kk=0;kk<16;kk++){
            const ulonglong2 b0 = *reinterpret_cast<const ulonglong2*>(&Bs[kk][tyn*16]);
            const ulonglong2 b1 = *reinterpret_cast<const ulonglong2*>(&Bs[kk][tyn*16+4]);
            const ulonglong2 b2 = *reinterpret_cast<const ulonglong2*>(&Bs[kk][tyn*16+8]);
            const ulonglong2 b3 = *reinterpret_cast<const ulonglong2*>(&Bs[kk][tyn*16+12]);
#pragma unroll
            for (int i=0;i<4;i++){
                unsigned long long ad = dup2(As[kk][txm + 32*i]);
                fma2(acc[i][0], ad, b0.x); fma2(acc[i][1], ad, b0.y);
                fma2(acc[i][2], ad, b1.x); fma2(acc[i][3], ad, b1.y);
                fma2(acc[i][4], ad, b2.x); fma2(acc[i][5], ad, b2.y);
                fma2(acc[i][6], ad, b3.x); fma2(acc[i][7], ad, b3.y);
            }
        }
        __syncthreads();
    }
#pragma unroll
    for (int i=0;i<4;i++){
        int m = m0 + txm + 32*i;
        int s = m >> 6, b = m & 63;
#pragma unroll
        for (int jp=0;jp<8;jp++){
            float2 v = *reinterpret_cast<float2*>(&acc[i][jp]);
            int n = n0 + tyn*16 + 2*jp;
            int dir = n >> 11, g = n & 2047;
            size_t base = ((((size_t)dir*SLEN) + s)*G4 + g)*BSZ + b;
            d_xg[base]       = v.x + d_bias[n];
            d_xg[base + BSZ] = v.y + d_bias[n+1];
        }
    }
}

// ---------------- persistent bidirectional LSTM ----------------
// 128 blocks x 256 threads, all co-resident (1 block/SM, smem-limited).
// block = (dir, 8 hidden units): 32 gate rows x 64 batches per step.
// W_hh slice stored DUPLICATED in smem: Wt[k][2r]=Wt[k][2r+1]=W[r][k] so the
// FFMA2 inner loop needs no register movs. Warp tile 16 rows x 16 batches:
// per kk per thread exactly 2x LDS.128 (both mostly broadcast) + 4x FFMA2.
// h staged from global (L2) into a triple-buffered smem pane, 1 sync/tile.
#define HS_STRIDE 72
#define HS_FLOATS (64*HS_STRIDE)                       // 4608
#define WT_FLOATS (512*64)                             // 32768 (128KB)
#define GS_OFF    (WT_FLOATS + 3*HS_FLOATS)            // 46592
#define LSTM_SMEM_FLOATS (GS_OFF + 32*HS_STRIDE)       // 48896 -> 195584 B

__global__ void __launch_bounds__(256,1) lstm_persist(const float* __restrict__ Whf,
                                                      const float* __restrict__ Whb)
{
    extern __shared__ float sm[];
    float* Wt = sm;                         // [512][64] duplicated rows
    float* Hs0 = sm + WT_FLOATS;
    float* Hs1 = Hs0 + HS_FLOATS;
    float* Hs2 = Hs1 + HS_FLOATS;
    float* Gs  = sm + GS_OFF;               // [32 rows][HS_STRIDE]
    float* bufp[3] = {Hs0, Hs1, Hs2};

    const int tid = threadIdx.x;
    const int dir = blockIdx.x >> 6;
    const int chunk = blockIdx.x & 63;
    const int j0 = chunk * 8;
    const int warp = tid >> 5, lane = tid & 31;
    const int rw0 = (warp >> 2) << 4;       // warp row offset (0/16)
    const int bw0 = (warp & 3) << 4;        // warp batch offset (0/16/32/48)
    const int rg  = lane >> 2;              // row-pair within warp (0..7)
    const int bq  = lane & 3;               // batch-quad within warp (0..3)
    const int wro = 2*rw0 + 4*rg;           // float offset into Wt row
    const int bro = bw0 + 4*bq;             // float offset into Hs row
    const int r0  = rw0 + 2*rg;             // first of the thread's 2 rows
    const float* W = dir ? Whb : Whf;

    // one-time duplicated weight load (coalesced global reads)
    for (int idx = tid; idx < 32*512; idx += 256){
        int r = idx >> 9, k = idx & 511;
        int gate = r >> 3, jj = r & 7;
        float w = W[(size_t)(gate*HID + j0 + jj)*HID + k];
        Wt[k*64 + 2*r]     = w;
        Wt[k*64 + 2*r + 1] = w;
    }
    __syncthreads();

    float creg[2] = {0.f, 0.f};

    for (int step = 0; step < SLEN; step++){
        int t = dir ? (SLEN-1-step) : step;

        // prefetch this step's xg contributions into registers
        float xv[2][4];
        {
            size_t xgb = (((size_t)dir*SLEN)+t)*G4*BSZ;
#pragma unroll
            for (int it=0; it<2; it++){
                int cell = tid + it*256;
                int jj = cell >> 6, b = cell & 63;
                int j = j0 + jj;
#pragma unroll
                for (int g=0; g<4; g++)
                    xv[it][g] = __ldg(&d_xg[xgb + (size_t)(g*HID+j)*BSZ + b]);
            }
        }

        unsigned long long a00=0ull, a01=0ull, a10=0ull, a11=0ull;

        if (step > 0){
            int tprev = dir ? (t+1) : (t-1);
            const float* hprev = d_hall + (((size_t)tprev*2 + dir)*HID)*BSZ;

            float4 st[4];
            // prime: tile0 -> buf0, tile1 -> regs
#pragma unroll
            for (int it=0; it<4; it++){
                int lin = tid + it*256;
                st[it] = __ldcg((const float4*)&hprev[(lin>>4)*64 + ((lin&15)<<2)]);
            }
#pragma unroll
            for (int it=0; it<4; it++){
                int lin = tid + it*256;
                *(float4*)&Hs0[(lin>>4)*HS_STRIDE + ((lin&15)<<2)] = st[it];
            }
#pragma unroll
            for (int it=0; it<4; it++){
                int lin = tid + it*256;
                st[it] = __ldcg((const float4*)&hprev[(64 + (lin>>4))*64 + ((lin&15)<<2)]);
            }

            for (int tile=0; tile<8; tile++){
                if (tile < 7){
                    float* wb = bufp[(tile+1)%3];
#pragma unroll
                    for (int it=0; it<4; it++){
                        int lin = tid + it*256;
                        *(float4*)&wb[(lin>>4)*HS_STRIDE + ((lin&15)<<2)] = st[it];
                    }
                }
                __syncthreads();
                if (tile < 6){
#pragma unroll
                    for (int it=0; it<4; it++){
                        int lin = tid + it*256;
                        st[it] = __ldcg((const float4*)&hprev[((tile+2)*64 + (lin>>4))*64 + ((lin&15)<<2)]);
                    }
                }
                const float* hb = bufp[tile%3];
                const float* wp = Wt + (tile*64)*64 + wro;
                const float* hp = hb + bro;
#pragma unroll 16
                for (int kk=0; kk<64; kk++){
                    ulonglong2 wv = *(const ulonglong2*)wp;   // (w_r0,w_r0),(w_r1,w_r1)
                    ulonglong2 hv = *(const ulonglong2*)hp;   // (h_b0,h_b1),(h_b2,h_b3)
                    fma2(a00, wv.x, hv.x); fma2(a01, wv.x, hv.y);
                    fma2(a10, wv.y, hv.x); fma2(a11, wv.y, hv.y);
                    wp += 64; hp += HS_STRIDE;
                }
            }
            // gate exchange through smem
            *(float2*)&Gs[(r0  )*HS_STRIDE + bro    ] = *(float2*)&a00;
            *(float2*)&Gs[(r0  )*HS_STRIDE + bro + 2] = *(float2*)&a01;
            *(float2*)&Gs[(r0+1)*HS_STRIDE + bro    ] = *(float2*)&a10;
            *(float2*)&Gs[(r0+1)*HS_STRIDE + bro + 2] = *(float2*)&a11;
            __syncthreads();
        }

#pragma unroll
        for (int it=0; it<2; it++){
            int cell = tid + it*256;
            int jj = cell >> 6, b = cell & 63;
            int j = j0 + jj;
            float g0, g1, g2, g3;
            if (step > 0){
                g0 = Gs[(     jj)*HS_STRIDE + b];
                g1 = Gs[( 8 + jj)*HS_STRIDE + b];
                g2 = Gs[(16 + jj)*HS_STRIDE + b];
                g3 = Gs[(24 + jj)*HS_STRIDE + b];
            } else { g0=g1=g2=g3=0.f; }
            float gi = g0 + xv[it][0];
            float gf = g1 + xv[it][1];
            float gg = g2 + xv[it][2];
            float go = g3 + xv[it][3];
            float ig = sigm(gi), fg = sigm(gf), og = sigm(go);
            float gt = tanhf(gg);
            float cn = fg*creg[it] + ig*gt;
            float hn = og * tanhf(cn);
            creg[it] = cn;
            d_hall[(((size_t)t*2 + dir)*HID + j)*BSZ + b] = hn;
        }

        // grid barrier: release increment + acquire poll
        __syncthreads();
        if (tid == 0){
            __threadfence();
            asm volatile("red.release.gpu.add.s32 [%0], %1;" :: "l"(&d_barCount), "r"(1) : "memory");
            int target = 128*(step+1);
            int v;
            do {
                asm volatile("ld.acquire.gpu.s32 %0, [%1];" : "=r"(v) : "l"(&d_barCount) : "memory");
            } while (v < target);
        }
        __syncthreads();
    }
}

// ---------------- batchnorm statistics: one block per feature ----------------
__global__ void bn_stats_kernel()
{
    int f = blockIdx.x;          // 0..1023
    int tid = threadIdx.x;       // 256 threads, one s-row each
    const float4* p = reinterpret_cast<const float4*>(&d_hall[((size_t)tid*2*HID + f)*BSZ]);
    float sum=0.f, sq=0.f;
#pragma unroll
    for (int i=0;i<16;i++){
        float4 v = p[i];
        sum += v.x+v.y+v.z+v.w;
        sq  += v.x*v.x + v.y*v.y + v.z*v.z + v.w*v.w;
    }
    __shared__ float ss[256], s2[256];
    ss[tid]=sum; s2[tid]=sq;
    __syncthreads();
    for (int o=128;o>0;o>>=1){
        if (tid<o){ ss[tid]+=ss[tid+o]; s2[tid]+=s2[tid+o]; }
        __syncthreads();
    }
    if (tid==0){
        float mean = ss[0] / (float)NROWS;
        float var  = s2[0] / (float)NROWS - mean*mean;
        d_mean[f] = mean;
        d_rstd[f] = rsqrtf(var + 1e-5f);
    }
}

// ---------------- fold BN into linear: A[t][f], Cc[t] ----------------
__global__ void ac_kernel(const float* __restrict__ gamma, const float* __restrict__ beta,
                          const float* __restrict__ lw, const float* __restrict__ lb)
{
    int t = blockIdx.x, tid = threadIdx.x;   // 17 blocks x 128
    float cs = 0.f;
    for (int f=tid; f<2*HID; f+=128){
        float sc = gamma[f]*d_rstd[f];
        float sh = beta[f] - d_mean[f]*sc;
        float w = lw[t*2*HID + f];
        d_A[t*2*HID + f] = w*sc;
        cs += sh*w;
    }
    __shared__ float red[128];
    red[tid]=cs; __syncthreads();
    for (int o=64;o>0;o>>=1){ if (tid<o) red[tid]+=red[tid+o]; __syncthreads(); }
    if (tid==0) d_Cc[t] = lb[t] + red[0];
}

// ---------------- emissions E[b][s][t]: 256 threads, 4-way f-split ----------------
__global__ void logits_kernel()
{
    __shared__ float As[NT][256];
    __shared__ float Ps[4][NT][64];
    int s = blockIdx.x;
    int tid = threadIdx.x;
    int b = tid & 63, sub = tid >> 6;    // sub covers a 64-wide f slice per chunk
    float acc[NT];
#pragma unroll
    for (int t=0;t<NT;t++) acc[t]=0.f;

    for (int f0=0; f0<2*HID; f0+=256){
        for (int idx=tid; idx<NT*256; idx+=256){
            int t = idx >> 8, fi = idx & 255;
            As[t][fi] = d_A[t*2*HID + f0 + fi];
        }
        __syncthreads();
        const float* hb = &d_hall[((size_t)s*2*HID + f0 + sub*64)*BSZ + b];
#pragma unroll 4
        for (int fi=0; fi<64; fi++){
            float hv = hb[(size_t)fi*BSZ];
#pragma unroll
            for (int t=0;t<NT;t++) acc[t] = fmaf(hv, As[t][sub*64+fi], acc[t]);
        }
        __syncthreads();
    }
#pragma unroll
    for (int t=0;t<NT;t++) Ps[sub][t][b] = acc[t];
    __syncthreads();
    if (sub == 0){
#pragma unroll
        for (int t=0;t<NT;t++){
            float v = acc[t] + Ps[1][t][b] + Ps[2][t][b] + Ps[3][t][b] + d_Cc[t];
            d_E[((size_t)b*SLEN + s)*NT + t] = v;
        }
    }
}

// ---------------- CRF: numerator, forward logZ, viterbi — one warp per batch ----------------
__global__ void crf_kernel(const int* __restrict__ labels, const float* __restrict__ start,
                           const float* __restrict__ endv, const float* __restrict__ trans,
                           float* __restrict__ out)
{
    int b = blockIdx.x;
    int lane = threadIdx.x;   // 32
    __shared__ float tr[NT*NT];
    __shared__ float alpha[NT], score[NT];
    for (int i=lane;i<NT*NT;i+=32) tr[i]=trans[i];
    __syncwarp();

    float numpart=0.f; int cnt=0;
    for (int s=lane; s<SLEN; s+=32){
        int m = d_maskI[s*BSZ + b];
        cnt += m;
        int ys = labels[s*BSZ + b];
        float emit = d_E[((size_t)b*SLEN + s)*NT + ys];
        if (s==0) numpart += start[ys] + emit;
        else if (m){
            int yp = labels[(s-1)*BSZ + b];
            numpart += tr[yp*NT + ys] + emit;
        }
    }
    for (int o=16;o>0;o>>=1){
        numpart += __shfl_down_sync(0xffffffffu, numpart, o);
        cnt     += __shfl_down_sync(0xffffffffu, cnt, o);
    }
    float num = 0.f;
    if (lane==0){
        int last = cnt - 1;
        num = numpart + endv[labels[last*BSZ + b]];
    }

    if (lane < NT){
        float a0 = start[lane] + d_E[((size_t)b*SLEN)*NT + lane];
        alpha[lane] = a0;
        score[lane] = a0;
    }
    __syncwarp();

    for (int s=1;s<SLEN;s++){
        float lse=0.f, best=0.f; int bp=0;
        if (lane < NT){
            float e = d_E[((size_t)b*SLEN + s)*NT + lane];
            float mx = -1e30f;
#pragma unroll
            for (int t1=0;t1<NT;t1++) mx = fmaxf(mx, alpha[t1] + tr[t1*NT + lane]);
            float sm = 0.f;
#pragma unroll
            for (int t1=0;t1<NT;t1++) sm += expf(alpha[t1] + tr[t1*NT + lane] - mx);
            lse = mx + logf(sm) + e;
            float bv = -1e30f;
#pragma unroll
            for (int t1=0;t1<NT;t1++){
                float v = score[t1] + tr[t1*NT + lane];
                if (v > bv){ bv = v; bp = t1; }
            }
            best = bv + e;
            d_bp[((size_t)b*SLEN + s)*NT + lane] = bp;
        }
        __syncwarp();
        if (lane < NT){
            int m = d_maskI[s*BSZ + b];
            if (m){ alpha[lane] = lse; score[lane] = best; }
        }
        __syncwarp();
    }

    float av = (lane<NT) ? alpha[lane] + endv[lane] : -1e30f;
    float mx = av;
    for (int o=16;o>0;o>>=1) mx = fmaxf(mx, __shfl_xor_sync(0xffffffffu, mx, o));
    float ex = (lane<NT) ? expf(av - mx) : 0.f;
    for (int o=16;o>0;o>>=1) ex += __shfl_xor_sync(0xffffffffu, ex, o);
    float Z = mx + logf(ex);
    if (lane==0) d_lossParts[b] = Z - num;

    if (lane==0){
        float bv=-1e30f; int tag=0;
        for (int t=0;t<NT;t++){
            float v = score[t] + endv[t];
            if (v > bv){ bv=v; tag=t; }
        }
        for (int s=SLEN-1; s>=1; --s){
            int m = d_maskI[s*BSZ + b];
            out[1 + b*SLEN + s] = m ? (float)tag : 0.f;
            tag = m ? d_bp[((size_t)b*SLEN + s)*NT + tag] : tag;
        }
        int m0 = d_maskI[b];
        out[1 + b*SLEN] = m0 ? (float)tag : 0.f;
    }
}

__global__ void loss_reduce_kernel(float* __restrict__ out)
{
    int l = threadIdx.x;   // 32
    float v = d_lossParts[l] + d_lossParts[l+32];
    for (int o=16;o>0;o>>=1) v += __shfl_xor_sync(0xffffffffu, v, o);
    if (l==0) out[0] = v;
}

// ---------------- launch ----------------
extern "C" void kernel_launch(void* const* d_in, const int* in_sizes, int n_in,
                              void* d_out, int out_size)
{
    const float* word   = (const float*)d_in[0];
    const void*  mask   = d_in[1];
    const int*   labels = (const int*)d_in[2];
    const float* w_ih_f = (const float*)d_in[3];
    const float* w_hh_f = (const float*)d_in[4];
    const float* b_ih_f = (const float*)d_in[5];
    const float* b_hh_f = (const float*)d_in[6];
    const float* w_ih_b = (const float*)d_in[7];
    const float* w_hh_b = (const float*)d_in[8];
    const float* b_ih_b = (const float*)d_in[9];
    const float* b_hh_b = (const float*)d_in[10];
    const float* gamma  = (const float*)d_in[11];
    const float* beta   = (const float*)d_in[12];
    const float* lin_w  = (const float*)d_in[13];
    const float* lin_b  = (const float*)d_in[14];
    const float* cstart = (const float*)d_in[15];
    const float* cend   = (const float*)d_in[16];
    const float* ctrans = (const float*)d_in[17];
    float* out = (float*)d_out;

    prep_kernel<<<256,256>>>(b_ih_f,b_hh_f,b_ih_b,b_hh_b, mask);

    dim3 g1(NCOLS/128, NROWS/128);     // (32, 128)
    gemm_xg_kernel<<<g1,256>>>(word, w_ih_f, w_ih_b);

    cudaFuncSetAttribute(lstm_persist, cudaFuncAttributeMaxDynamicSharedMemorySize,
                         LSTM_SMEM_FLOATS*4);
    lstm_persist<<<128,256,LSTM_SMEM_FLOATS*4>>>(w_hh_f, w_hh_b);

    bn_stats_kernel<<<2*HID,256>>>();
    ac_kernel<<<NT,128>>>(gamma,beta,lin_w,lin_b);
    logits_kernel<<<SLEN,256>>>();
    crf_kernel<<<BSZ,32>>>(labels, cstart, cend, ctrans, out);
    loss_reduce_kernel<<<1,32>>>(out);
}